// round 8
// baseline (speedup 1.0000x reference)
#include <cuda_runtime.h>

#define NROWS 8192
#define CCOLS 2048
#define BINS  30
#define TOTF  8192.0f  /* tot = max(N,1) */
#define RPB   256      /* rows per block in fused pass */
#define TPB   128      /* threads per block = columns per block */
#define YBLK  (NROWS / RPB)   /* 32 row-chunk slabs */

// Scratch (no cudaMalloc allowed).
// g_part[y][b][c]: per-row-chunk partial (bce_sum, count) — written with plain
// coalesced stores, NO atomics. 32*30*2048*8B = 15.7 MB.
__device__ float2 g_part[YBLK * BINS * CCOLS];
__device__ float  g_cnt[BINS * CCOLS];
__device__ float  g_sum[BINS * CCOLS];

// bin = clip(floor(30*|sigmoid(p)-t|), 0, 29)
// |sigmoid(p)-t| = sigmoid(s), s = p*(1-2t) for t in {0,1}
// 30*sigmoid(s) = 15*tanh(s/2) + 15  -> single MUFU.TANH
__device__ __forceinline__ int bin_of_s(float s) {
    float u;
    asm("tanh.approx.f32 %0, %1;" : "=f"(u) : "f"(0.5f * s));
    int b = __float2int_rd(fmaf(15.0f, u, 15.0f));
    return min(max(b, 0), BINS - 1);
}

// ---------------------------------------------------------------- K1: fused histogram + BCE-sum
// Single pass over preds/targets. Each thread owns one column; per-column
// (sum,count) accumulators per bin live in shared as float2 -> conflict-free,
// no atomics, no __syncthreads. Flush = private slab store (coalesced STG.64).
__global__ __launch_bounds__(TPB) void fused_kernel(const float* __restrict__ preds,
                                                    const int*   __restrict__ targets) {
    __shared__ float2 sh[BINS][TPB];   // 30*128*8 = 30720 B
    const int tid = threadIdx.x;
    const int c   = blockIdx.x * TPB + tid;
    const int r0  = blockIdx.y * RPB;

#pragma unroll
    for (int b = 0; b < BINS; b++) sh[b][tid] = make_float2(0.0f, 0.0f);

    const float* pp = preds   + (size_t)r0 * CCOLS + c;
    const int*   tp = targets + (size_t)r0 * CCOLS + c;

#pragma unroll 8
    for (int r = 0; r < RPB; r++) {
        float p = pp[(size_t)r * CCOLS];
        float t = (float)tp[(size_t)r * CCOLS];
        // s = p*(1-2t);  bce = softplus(p) - p*t = softplus(s)
        float s = p * fmaf(-2.0f, t, 1.0f);
        int   b = bin_of_s(s);
        float as  = fabsf(s);
        float e   = __expf(-as);
        float bce = fmaxf(s, 0.0f) + __logf(1.0f + e);
        float2 v = sh[b][tid];
        v.x += bce;
        v.y += 1.0f;
        sh[b][tid] = v;
    }

    // flush: plain coalesced stores into this row-chunk's private slab
    float2* dst = g_part + (size_t)blockIdx.y * (BINS * CCOLS) + c;
#pragma unroll
    for (int b = 0; b < BINS; b++) {
        dst[b * CCOLS] = sh[b][tid];
    }
}

// ---------------------------------------------------------------- K2: reduce slabs
// g_sum/g_cnt[i] = sum over 32 row-chunk partials. Also zeroes out[0].
__global__ __launch_bounds__(256) void reduce_kernel(float* __restrict__ out) {
    const int i = blockIdx.x * 256 + threadIdx.x;   // i < BINS*CCOLS = 61440
    if (i == 0) out[0] = 0.0f;
    float s = 0.0f, n = 0.0f;
#pragma unroll 8
    for (int y = 0; y < YBLK; y++) {
        float2 v = g_part[(size_t)y * (BINS * CCOLS) + i];
        s += v.x;
        n += v.y;
    }
    g_sum[i] = s;
    g_cnt[i] = n;
}

// ---------------------------------------------------------------- K3: finalize
// loss = (1/(N*C)) * sum_c [ (TOT / max(n_c,1)) * sum_b S[b][c] / acc_new[b][c] ]
__global__ __launch_bounds__(256) void finalize_kernel(const float* __restrict__ acc_sum,
                                                       float* __restrict__ out,
                                                       float scale) {
    const int c = blockIdx.x * 256 + threadIdx.x;

    float n = 0.0f;
#pragma unroll
    for (int b = 0; b < BINS; b++) n += (g_cnt[b * CCOLS + c] >= 1.0f) ? 1.0f : 0.0f;
    float inv_n = 1.0f / fmaxf(n, 1.0f);

    float colsum = 0.0f;
#pragma unroll
    for (int b = 0; b < BINS; b++) {
        float cnt = g_cnt[b * CCOLS + c];
        if (cnt > 0.0f) {
            float accn = fmaf(0.25f, cnt, 0.75f * acc_sum[b * CCOLS + c]);
            colsum += g_sum[b * CCOLS + c] / accn;   // accn >= 0.25 when cnt>0
        }
    }
    float acc = colsum * (TOTF * inv_n) * scale;

    // block reduction -> one atomic per block (8 total atomics)
#pragma unroll
    for (int o = 16; o > 0; o >>= 1) acc += __shfl_down_sync(0xffffffffu, acc, o);
    __shared__ float sw[8];
    int lane = threadIdx.x & 31, wid = threadIdx.x >> 5;
    if (lane == 0) sw[wid] = acc;
    __syncthreads();
    if (wid == 0) {
        acc = (lane < 8) ? sw[lane] : 0.0f;
#pragma unroll
        for (int o = 4; o > 0; o >>= 1) acc += __shfl_down_sync(0xffffffffu, acc, o);
        if (lane == 0) atomicAdd(out, acc);
    }
}

// ---------------------------------------------------------------- launch
extern "C" void kernel_launch(void* const* d_in, const int* in_sizes, int n_in,
                              void* d_out, int out_size) {
    const float* preds   = (const float*)d_in[0];   // [8192, 2048] f32
    const int*   targets = (const int*)  d_in[1];   // [8192, 2048] i32
    const float* acc_sum = (const float*)d_in[2];   // [30, 2048]   f32
    float* out = (float*)d_out;                     // scalar loss

    // K1: single fused pass, atomic-free (16 col-tiles x 32 row-chunks)
    dim3 fgrid(CCOLS / TPB, NROWS / RPB);
    fused_kernel<<<fgrid, TPB>>>(preds, targets);

    // K2: fold 32 partial slabs -> g_sum/g_cnt, zero out
    reduce_kernel<<<(BINS * CCOLS) / 256, 256>>>(out);

    // K3: finalize (tiny)
    const float scale = 1.0f / ((float)NROWS * (float)CCOLS);  // LOSS_WEIGHT = 1
    finalize_kernel<<<CCOLS / 256, 256>>>(acc_sum, out, scale);
}